// round 1
// baseline (speedup 1.0000x reference)
#include <cuda_runtime.h>
#include <math.h>

#define NQ 8192
#define NKK 2048
#define DD  2048
#define DVV 2048

// 64 MB scratch for the score / probability matrix (allocation-free rule:
// __device__ global array).
__device__ float g_S[(size_t)NQ * NKK];

// ---------------------------------------------------------------------------
// SGEMM: C[M,N] = alpha * A[M,K] @ op(B)
//   TRANS_B = true : B is [N,K] row-major (C = A * B^T)   -> pass 1 (Key)
//   TRANS_B = false: B is [K,N] row-major (C = A * B)     -> pass 3 (Value)
// Block tile 128x128, K-chunk 16, 256 threads, 8x8 per-thread microtile,
// double-buffered shared memory. Dimensions assumed multiples of tile sizes
// (true here: 8192/2048/2048).
// ---------------------------------------------------------------------------
template <bool TRANS_B>
__global__ __launch_bounds__(256, 2) void sgemm128(
    const float* __restrict__ A, const float* __restrict__ B,
    float* __restrict__ C, int M, int N, int K, float alpha)
{
    constexpr int BM = 128, BN = 128, BK = 16;

    __shared__ float As[2][BK][BM];
    __shared__ float Bs[2][BK][BN];

    const int tid = threadIdx.x;
    const int bm  = blockIdx.y * BM;
    const int bn  = blockIdx.x * BN;

    // A-tile loader mapping: 64 rows per pass, float4 along K
    const int a_row = tid >> 2;         // 0..63
    const int a_col = (tid & 3) << 2;   // 0,4,8,12

    // B-tile loader mapping (NN case): 8 K-rows per pass, float4 along N
    const int b_row_nn = tid >> 5;          // 0..7
    const int b_col_nn = (tid & 31) << 2;   // 0..124

    // compute mapping
    const int ty   = tid >> 4;          // 0..15
    const int tx   = tid & 15;          // 0..15
    const int row0 = ty * 8;
    const int col0 = tx * 8;

    float acc[8][8];
#pragma unroll
    for (int i = 0; i < 8; ++i)
#pragma unroll
        for (int j = 0; j < 8; ++j) acc[i][j] = 0.0f;

    float a_l[2][4];
    float b_l[2][4];

    auto ld_global = [&](int k0) {
#pragma unroll
        for (int g = 0; g < 2; ++g) {
            const float4 va = *reinterpret_cast<const float4*>(
                &A[(size_t)(bm + a_row + g * 64) * K + k0 + a_col]);
            a_l[g][0] = va.x; a_l[g][1] = va.y; a_l[g][2] = va.z; a_l[g][3] = va.w;
        }
        if (TRANS_B) {
#pragma unroll
            for (int g = 0; g < 2; ++g) {
                const float4 vb = *reinterpret_cast<const float4*>(
                    &B[(size_t)(bn + a_row + g * 64) * K + k0 + a_col]);
                b_l[g][0] = vb.x; b_l[g][1] = vb.y; b_l[g][2] = vb.z; b_l[g][3] = vb.w;
            }
        } else {
#pragma unroll
            for (int g = 0; g < 2; ++g) {
                const float4 vb = *reinterpret_cast<const float4*>(
                    &B[(size_t)(k0 + b_row_nn + g * 8) * N + bn + b_col_nn]);
                b_l[g][0] = vb.x; b_l[g][1] = vb.y; b_l[g][2] = vb.z; b_l[g][3] = vb.w;
            }
        }
    };

    auto st_smem = [&](int buf) {
#pragma unroll
        for (int g = 0; g < 2; ++g)
#pragma unroll
            for (int i = 0; i < 4; ++i)
                As[buf][a_col + i][a_row + g * 64] = a_l[g][i];
        if (TRANS_B) {
#pragma unroll
            for (int g = 0; g < 2; ++g)
#pragma unroll
                for (int i = 0; i < 4; ++i)
                    Bs[buf][a_col + i][a_row + g * 64] = b_l[g][i];
        } else {
#pragma unroll
            for (int g = 0; g < 2; ++g)
                *reinterpret_cast<float4*>(&Bs[buf][b_row_nn + g * 8][b_col_nn]) =
                    make_float4(b_l[g][0], b_l[g][1], b_l[g][2], b_l[g][3]);
        }
    };

    ld_global(0);
    st_smem(0);
    __syncthreads();

    const int nt = K / BK;
    for (int t = 0; t < nt; ++t) {
        const int buf = t & 1;
        if (t + 1 < nt) ld_global((t + 1) * BK);

#pragma unroll
        for (int k = 0; k < BK; ++k) {
            const float4 a0 = *reinterpret_cast<const float4*>(&As[buf][k][row0]);
            const float4 a1 = *reinterpret_cast<const float4*>(&As[buf][k][row0 + 4]);
            const float4 b0 = *reinterpret_cast<const float4*>(&Bs[buf][k][col0]);
            const float4 b1 = *reinterpret_cast<const float4*>(&Bs[buf][k][col0 + 4]);
            const float av[8] = {a0.x, a0.y, a0.z, a0.w, a1.x, a1.y, a1.z, a1.w};
            const float bv[8] = {b0.x, b0.y, b0.z, b0.w, b1.x, b1.y, b1.z, b1.w};
#pragma unroll
            for (int i = 0; i < 8; ++i)
#pragma unroll
                for (int j = 0; j < 8; ++j)
                    acc[i][j] = fmaf(av[i], bv[j], acc[i][j]);
        }

        if (t + 1 < nt) st_smem(buf ^ 1);
        __syncthreads();
    }

#pragma unroll
    for (int i = 0; i < 8; ++i) {
        float* cp = &C[(size_t)(bm + row0 + i) * N + bn + col0];
#pragma unroll
        for (int j4 = 0; j4 < 2; ++j4) {
            float4 v;
            v.x = acc[i][j4 * 4 + 0] * alpha;
            v.y = acc[i][j4 * 4 + 1] * alpha;
            v.z = acc[i][j4 * 4 + 2] * alpha;
            v.w = acc[i][j4 * 4 + 3] * alpha;
            *reinterpret_cast<float4*>(cp + j4 * 4) = v;
        }
    }
}

// ---------------------------------------------------------------------------
// Masked softmax, in place on g_S.
// att[q,k] = mask*exp(s - rowmax) / sum_k(mask*exp(s - rowmax))
// (the plain-softmax denominator cancels in the reference's renormalization)
// One block (256 threads) per row of 2048; each thread holds 8 elements.
// ---------------------------------------------------------------------------
__global__ void masked_softmax_kernel(const float* __restrict__ mask)
{
    const int row = blockIdx.x;
    float* s = g_S + (size_t)row * NKK;
    const float* mrow = mask + (size_t)row * NKK;
    const int tid = threadIdx.x;

    float v[8], mk[8];
#pragma unroll
    for (int j = 0; j < 2; ++j) {
        const float4 t4 = *reinterpret_cast<const float4*>(&s[tid * 8 + j * 4]);
        v[j * 4 + 0] = t4.x; v[j * 4 + 1] = t4.y; v[j * 4 + 2] = t4.z; v[j * 4 + 3] = t4.w;
        const float4 m4 = *reinterpret_cast<const float4*>(&mrow[tid * 8 + j * 4]);
        mk[j * 4 + 0] = m4.x; mk[j * 4 + 1] = m4.y; mk[j * 4 + 2] = m4.z; mk[j * 4 + 3] = m4.w;
    }

    // row max (over all entries: valid since any shift works for stability)
    float mx = -1e30f;
#pragma unroll
    for (int j = 0; j < 8; ++j) mx = fmaxf(mx, v[j]);
#pragma unroll
    for (int o = 16; o > 0; o >>= 1)
        mx = fmaxf(mx, __shfl_xor_sync(0xFFFFFFFFu, mx, o));

    __shared__ float red[8];
    const int wid  = tid >> 5;
    const int lane = tid & 31;
    if (lane == 0) red[wid] = mx;
    __syncthreads();
    float bmax = red[0];
#pragma unroll
    for (int w = 1; w < 8; ++w) bmax = fmaxf(bmax, red[w]);
    __syncthreads();

    // masked exp + row sum
    float sum = 0.0f;
#pragma unroll
    for (int j = 0; j < 8; ++j) {
        v[j] = mk[j] * __expf(v[j] - bmax);
        sum += v[j];
    }
#pragma unroll
    for (int o = 16; o > 0; o >>= 1)
        sum += __shfl_xor_sync(0xFFFFFFFFu, sum, o);
    if (lane == 0) red[wid] = sum;
    __syncthreads();
    float bsum = 0.0f;
#pragma unroll
    for (int w = 0; w < 8; ++w) bsum += red[w];

    const float inv = 1.0f / bsum;
#pragma unroll
    for (int j = 0; j < 2; ++j) {
        float4 o4;
        o4.x = v[j * 4 + 0] * inv;
        o4.y = v[j * 4 + 1] * inv;
        o4.z = v[j * 4 + 2] * inv;
        o4.w = v[j * 4 + 3] * inv;
        *reinterpret_cast<float4*>(&s[tid * 8 + j * 4]) = o4;
    }
}

// ---------------------------------------------------------------------------
extern "C" void kernel_launch(void* const* d_in, const int* in_sizes, int n_in,
                              void* d_out, int out_size)
{
    const float* Q    = (const float*)d_in[0];  // [NQ, D]
    const float* Km   = (const float*)d_in[1];  // [NK, D]
    const float* V    = (const float*)d_in[2];  // [NK, DV]
    const float* mask = (const float*)d_in[3];  // [NQ, NK]
    float* O = (float*)d_out;                   // [NQ, DV]

    float* Sptr = nullptr;
    cudaGetSymbolAddress((void**)&Sptr, g_S);

    const float scale = 1.0f / sqrtf((float)DD);

    // Pass 1: S = scale * Q @ K^T   (NT gemm: M=NQ, N=NK, K=D)
    {
        dim3 grid(NKK / 128, NQ / 128);
        sgemm128<true><<<grid, 256>>>(Q, Km, Sptr, NQ, NKK, DD, scale);
    }

    // Pass 2: masked softmax rows, in place
    masked_softmax_kernel<<<NQ, 256>>>(mask);

    // Pass 3: O = P @ V   (NN gemm: M=NQ, N=DV, K=NK)
    {
        dim3 grid(DVV / 128, NQ / 128);
        sgemm128<false><<<grid, 256>>>(Sptr, V, O, NQ, DVV, NKK, 1.0f);
    }
}

// round 3
// speedup vs baseline: 4.0041x; 4.0041x over previous
#include <cuda_runtime.h>
#include <math.h>
#include <stdint.h>

#define NQ  8192
#define NKK 2048
#define DD  2048
#define DVV 2048

// ---------------------------------------------------------------------------
// Scratch (allocation-free rule: __device__ globals)
// ---------------------------------------------------------------------------
__device__ float g_S [(size_t)NQ  * NKK];   // scores / probabilities (64 MB)
__device__ float g_Qr[(size_t)NQ  * DD ];   // Q rounded to tf32      (64 MB)
__device__ float g_Kr[(size_t)NKK * DD ];   // K rounded to tf32      (16 MB)
__device__ float g_Vr[(size_t)NKK * DVV];   // V rounded to tf32      (16 MB)

__device__ __forceinline__ float round_tf32(float x) {
    uint32_t u;
    asm("cvt.rna.tf32.f32 %0, %1;" : "=r"(u) : "f"(x));
    return __uint_as_float(u);
}

__device__ __forceinline__ uint32_t smem_u32(const void* p) {
    uint32_t a;
    asm("{ .reg .u64 t; cvta.to.shared.u64 t, %1; cvt.u32.u64 %0, t; }"
        : "=r"(a) : "l"(p));
    return a;
}

#define CP_ASYNC16(dst, src) \
    asm volatile("cp.async.cg.shared.global [%0], [%1], 16;" \
                 :: "r"(dst), "l"(src) : "memory")
#define CP_COMMIT()  asm volatile("cp.async.commit_group;" ::: "memory")
#define CP_WAIT(n)   asm volatile("cp.async.wait_group %0;" :: "n"(n) : "memory")

__device__ __forceinline__ void mma_tf32(
    float* c, const uint32_t* a, const uint32_t* b)
{
    asm volatile(
        "mma.sync.aligned.m16n8k8.row.col.f32.tf32.tf32.f32 "
        "{%0,%1,%2,%3}, {%4,%5,%6,%7}, {%8,%9}, {%0,%1,%2,%3};"
        : "+f"(c[0]), "+f"(c[1]), "+f"(c[2]), "+f"(c[3])
        : "r"(a[0]), "r"(a[1]), "r"(a[2]), "r"(a[3]), "r"(b[0]), "r"(b[1]));
}

// ---------------------------------------------------------------------------
// Tensor-core tf32 GEMM:  C[M,N] = alpha * A[M,K] @ op(B)
//   TRANS_B = true : B is [N,K] row-major (C = A * B^T)   -> pass 1
//   TRANS_B = false: B is [K,N] row-major (C = A * B)     -> pass 3
// Block tile 128x128x32, 256 threads (8 warps, 4x2), warp tile 32x64,
// mma.sync m16n8k8 tf32, cp.async double-buffered shared memory.
// Inputs must be pre-rounded to tf32 (RNA).
// ---------------------------------------------------------------------------
#define BM 128
#define BN 128
#define BK 32
#define A_STRIDE 36                     // BK + 4 pad (floats)
#define BNN_STRIDE 132                  // BN + 4 pad (floats)
#define A_FLOATS (BM * A_STRIDE)        // 4608
#define BT_FLOATS (BN * A_STRIDE)       // 4608
#define BNNS_FLOATS (BK * BNN_STRIDE)   // 4224

template <bool TRANS_B>
__global__ __launch_bounds__(256, 2) void mma_gemm(
    const float* __restrict__ A, const float* __restrict__ B,
    float* __restrict__ C, int M, int N, int K, float alpha)
{
    extern __shared__ float sm[];
    constexpr int B_FLOATS = TRANS_B ? BT_FLOATS : BNNS_FLOATS;
    constexpr int STAGE_FLOATS = A_FLOATS + B_FLOATS;

    const int tid  = threadIdx.x;
    const int wid  = tid >> 5;
    const int lane = tid & 31;
    const int g    = lane >> 2;   // groupID
    const int t4   = lane & 3;    // threadID in group

    const int m0 = blockIdx.y * BM;
    const int n0 = blockIdx.x * BN;
    const int wm0 = (wid >> 1) * 32;   // warp tile row (4 warps in M)
    const int wn0 = (wid & 1) * 64;    // warp tile col (2 warps in N)

    const uint32_t sbase = smem_u32(sm);

    // ---- async tile loaders (all 256 threads, 4 x 16B each for A and B) ----
    auto load_tiles = [&](int stage, int k0) {
        const uint32_t abase = sbase + stage * STAGE_FLOATS * 4;
        const uint32_t bbase = abase + A_FLOATS * 4;
#pragma unroll
        for (int i = 0; i < 4; ++i) {
            const int cid = tid + i * 256;          // 0..1023
            {   // A tile: 128 rows x 8 16B-chunks, dst [m][k]
                const int r = cid >> 3, c = cid & 7;
                CP_ASYNC16(abase + (r * A_STRIDE + c * 4) * 4,
                           A + (size_t)(m0 + r) * K + k0 + c * 4);
            }
            if (TRANS_B) {                          // B [N,K]: dst [n][k]
                const int r = cid >> 3, c = cid & 7;
                CP_ASYNC16(bbase + (r * A_STRIDE + c * 4) * 4,
                           B + (size_t)(n0 + r) * K + k0 + c * 4);
            } else {                                // B [K,N]: dst [k][n]
                const int r = cid >> 5, c = cid & 31;
                CP_ASYNC16(bbase + (r * BNN_STRIDE + c * 4) * 4,
                           B + (size_t)(k0 + r) * N + n0 + c * 4);
            }
        }
        CP_COMMIT();
    };

    float acc[2][8][4];
#pragma unroll
    for (int i = 0; i < 2; ++i)
#pragma unroll
        for (int j = 0; j < 8; ++j)
#pragma unroll
            for (int k = 0; k < 4; ++k) acc[i][j][k] = 0.0f;

    const int nt = K / BK;
    load_tiles(0, 0);

    for (int tile = 0; tile < nt; ++tile) {
        if (tile + 1 < nt) {
            load_tiles((tile + 1) & 1, (tile + 1) * BK);
            CP_WAIT(1);
        } else {
            CP_WAIT(0);
        }
        __syncthreads();

        const float* As = sm + (tile & 1) * STAGE_FLOATS;
        const float* Bs = As + A_FLOATS;
        const uint32_t* Au = reinterpret_cast<const uint32_t*>(As);
        const uint32_t* Bu = reinterpret_cast<const uint32_t*>(Bs);

#pragma unroll
        for (int ks = 0; ks < 4; ++ks) {
            const int k0 = ks * 8;
            uint32_t af[2][4];
#pragma unroll
            for (int mt = 0; mt < 2; ++mt) {
                const int mr = wm0 + mt * 16 + g;
                af[mt][0] = Au[(mr    ) * A_STRIDE + k0 + t4    ];
                af[mt][1] = Au[(mr + 8) * A_STRIDE + k0 + t4    ];
                af[mt][2] = Au[(mr    ) * A_STRIDE + k0 + t4 + 4];
                af[mt][3] = Au[(mr + 8) * A_STRIDE + k0 + t4 + 4];
            }
            uint32_t bf[8][2];
#pragma unroll
            for (int nt2 = 0; nt2 < 8; ++nt2) {
                const int nc = wn0 + nt2 * 8 + g;
                if (TRANS_B) {
                    bf[nt2][0] = Bu[nc * A_STRIDE + k0 + t4    ];
                    bf[nt2][1] = Bu[nc * A_STRIDE + k0 + t4 + 4];
                } else {
                    bf[nt2][0] = Bu[(k0 + t4    ) * BNN_STRIDE + nc];
                    bf[nt2][1] = Bu[(k0 + t4 + 4) * BNN_STRIDE + nc];
                }
            }
#pragma unroll
            for (int mt = 0; mt < 2; ++mt)
#pragma unroll
                for (int nt2 = 0; nt2 < 8; ++nt2)
                    mma_tf32(acc[mt][nt2], af[mt], bf[nt2]);
        }
        __syncthreads();
    }

    // ---- epilogue: c0,c1 at (row, tig*2), c2,c3 at (row+8, tig*2) ----
#pragma unroll
    for (int mt = 0; mt < 2; ++mt) {
        const int row = m0 + wm0 + mt * 16 + g;
#pragma unroll
        for (int nt2 = 0; nt2 < 8; ++nt2) {
            const int col = n0 + wn0 + nt2 * 8 + t4 * 2;
            float2 v0 = make_float2(acc[mt][nt2][0] * alpha, acc[mt][nt2][1] * alpha);
            float2 v1 = make_float2(acc[mt][nt2][2] * alpha, acc[mt][nt2][3] * alpha);
            *reinterpret_cast<float2*>(&C[(size_t)row * N + col]) = v0;
            *reinterpret_cast<float2*>(&C[(size_t)(row + 8) * N + col]) = v1;
        }
    }
}

// ---------------------------------------------------------------------------
// tf32 rounding pre-pass
// ---------------------------------------------------------------------------
__global__ void round_tf32_kernel(const float4* __restrict__ in,
                                  float4* __restrict__ out, int n4)
{
    int i = blockIdx.x * blockDim.x + threadIdx.x;
    if (i < n4) {
        float4 v = in[i];
        v.x = round_tf32(v.x); v.y = round_tf32(v.y);
        v.z = round_tf32(v.z); v.w = round_tf32(v.w);
        out[i] = v;
    }
}

// ---------------------------------------------------------------------------
// Masked softmax (in place on g_S), output rounded to tf32 for GEMM2.
// att[q,k] = mask*exp(s - rowmax) / sum(mask*exp(s - rowmax))
// (plain-softmax denominator cancels under the reference's renormalization)
// ---------------------------------------------------------------------------
__global__ void masked_softmax_kernel(const float* __restrict__ mask)
{
    const int row = blockIdx.x;
    float* s = g_S + (size_t)row * NKK;
    const float* mrow = mask + (size_t)row * NKK;
    const int tid = threadIdx.x;

    float v[8], mk[8];
#pragma unroll
    for (int j = 0; j < 2; ++j) {
        const float4 t4 = *reinterpret_cast<const float4*>(&s[tid * 8 + j * 4]);
        v[j * 4 + 0] = t4.x; v[j * 4 + 1] = t4.y; v[j * 4 + 2] = t4.z; v[j * 4 + 3] = t4.w;
        const float4 m4 = *reinterpret_cast<const float4*>(&mrow[tid * 8 + j * 4]);
        mk[j * 4 + 0] = m4.x; mk[j * 4 + 1] = m4.y; mk[j * 4 + 2] = m4.z; mk[j * 4 + 3] = m4.w;
    }

    float mx = -1e30f;
#pragma unroll
    for (int j = 0; j < 8; ++j) mx = fmaxf(mx, v[j]);
#pragma unroll
    for (int o = 16; o > 0; o >>= 1)
        mx = fmaxf(mx, __shfl_xor_sync(0xFFFFFFFFu, mx, o));

    __shared__ float red[8];
    const int wid = tid >> 5, lane = tid & 31;
    if (lane == 0) red[wid] = mx;
    __syncthreads();
    float bmax = red[0];
#pragma unroll
    for (int w = 1; w < 8; ++w) bmax = fmaxf(bmax, red[w]);
    __syncthreads();

    float sum = 0.0f;
#pragma unroll
    for (int j = 0; j < 8; ++j) {
        v[j] = mk[j] * __expf(v[j] - bmax);
        sum += v[j];
    }
#pragma unroll
    for (int o = 16; o > 0; o >>= 1)
        sum += __shfl_xor_sync(0xFFFFFFFFu, sum, o);
    if (lane == 0) red[wid] = sum;
    __syncthreads();
    float bsum = 0.0f;
#pragma unroll
    for (int w = 0; w < 8; ++w) bsum += red[w];

    const float inv = 1.0f / bsum;
#pragma unroll
    for (int j = 0; j < 2; ++j) {
        float4 o4;
        o4.x = round_tf32(v[j * 4 + 0] * inv);
        o4.y = round_tf32(v[j * 4 + 1] * inv);
        o4.z = round_tf32(v[j * 4 + 2] * inv);
        o4.w = round_tf32(v[j * 4 + 3] * inv);
        *reinterpret_cast<float4*>(&s[tid * 8 + j * 4]) = o4;
    }
}

// ---------------------------------------------------------------------------
extern "C" void kernel_launch(void* const* d_in, const int* in_sizes, int n_in,
                              void* d_out, int out_size)
{
    (void)in_sizes; (void)n_in; (void)out_size;
    const float* Q    = (const float*)d_in[0];  // [NQ, D]
    const float* Km   = (const float*)d_in[1];  // [NK, D]
    const float* V    = (const float*)d_in[2];  // [NK, DV]
    const float* mask = (const float*)d_in[3];  // [NQ, NK]
    float* O = (float*)d_out;                   // [NQ, DV]

    float *Sp, *Qr, *Kr, *Vr;
    cudaGetSymbolAddress((void**)&Sp, g_S);
    cudaGetSymbolAddress((void**)&Qr, g_Qr);
    cudaGetSymbolAddress((void**)&Kr, g_Kr);
    cudaGetSymbolAddress((void**)&Vr, g_Vr);

    const int smem_t  = (A_FLOATS + BT_FLOATS)   * 2 * 4;  // 73728 B
    const int smem_nn = (A_FLOATS + BNNS_FLOATS) * 2 * 4;  // 70656 B
    cudaFuncSetAttribute(mma_gemm<true>,
                         cudaFuncAttributeMaxDynamicSharedMemorySize, smem_t);
    cudaFuncSetAttribute(mma_gemm<false>,
                         cudaFuncAttributeMaxDynamicSharedMemorySize, smem_nn);

    const float scale = 1.0f / sqrtf((float)DD);

    // pre-passes: RNA-round operands to tf32
    {
        int n4q = (NQ * DD) / 4;
        round_tf32_kernel<<<(n4q + 255) / 256, 256>>>((const float4*)Q, (float4*)Qr, n4q);
        int n4k = (NKK * DD) / 4;
        round_tf32_kernel<<<(n4k + 255) / 256, 256>>>((const float4*)Km, (float4*)Kr, n4k);
        int n4v = (NKK * DVV) / 4;
        round_tf32_kernel<<<(n4v + 255) / 256, 256>>>((const float4*)V, (float4*)Vr, n4v);
    }

    // GEMM1: S = scale * Qr @ Kr^T  (NT)
    {
        dim3 grid(NKK / BN, NQ / BM);
        mma_gemm<true><<<grid, 256, smem_t>>>(Qr, Kr, Sp, NQ, NKK, DD, scale);
    }

    // masked softmax (emits tf32-rounded P in place)
    masked_softmax_kernel<<<NQ, 256>>>(mask);

    // GEMM2: O = P @ Vr  (NN)
    {
        dim3 grid(DVV / BN, NQ / BM);
        mma_gemm<false><<<grid, 256, smem_nn>>>(Sp, Vr, O, NQ, DVV, NKK, 1.0f);
    }
}